// round 3
// baseline (speedup 1.0000x reference)
#include <cuda_runtime.h>

// EuclideanLoss: loss = mean_n [ w_n * mean_b ||x[b,n,:] - y[b,:,n]||_2 ]
//   x: [B=32, N=8192, D=64] f32   (d_in[0])
//   y: [B=32, D=64, N=8192] f32   (d_in[1])
//   w_n = 1.5 for n in {1,2}, else 1.0
// Separable: loss = (1/(B*N)) * sum_{b,n} w_n * sqrt(sum_d diff^2)
// Single fused kernel: streaming pass + last-block-done deterministic reduction
// (atomic counter only ELECTS the finishing block; the summation order of the
// 1024 partials is fixed, so the result is bit-stable across graph replays).

#define B_DIM 32
#define N_DIM 8192
#define D_DIM 64
#define THREADS 256
#define NBLK ((B_DIM * N_DIM) / THREADS)   // 1024 blocks

__device__ float g_partials[NBLK];
__device__ unsigned int g_count = 0;       // reset by the last block each call

__global__ __launch_bounds__(THREADS)
void euclid_fused_kernel(const float* __restrict__ x, const float* __restrict__ y,
                         float* __restrict__ out) {
    const int t = blockIdx.x * THREADS + threadIdx.x;   // 0 .. B*N-1
    const int b = t >> 13;          // t / N_DIM
    const int n = t & (N_DIM - 1);  // t % N_DIM

    // x row: contiguous 64 floats, 16x LDG.128; every fetched sector is
    // consumed by the same thread's unrolled loads (L1 hits) -> full DRAM eff.
    const float4* __restrict__ xp =
        reinterpret_cast<const float4*>(x + ((size_t)b * N_DIM + n) * D_DIM);
    // y column: stride N_DIM per d, consecutive threads -> consecutive n
    // => each (b,d) warp load is one perfectly coalesced 128B transaction.
    const float* __restrict__ yp = y + (size_t)b * D_DIM * N_DIM + n;

    float acc = 0.0f;
#pragma unroll
    for (int i = 0; i < D_DIM / 4; ++i) {
        float4 xv = xp[i];
        float y0 = yp[(size_t)(4 * i + 0) * N_DIM];
        float y1 = yp[(size_t)(4 * i + 1) * N_DIM];
        float y2 = yp[(size_t)(4 * i + 2) * N_DIM];
        float y3 = yp[(size_t)(4 * i + 3) * N_DIM];
        float d0 = xv.x - y0;
        float d1 = xv.y - y1;
        float d2 = xv.z - y2;
        float d3 = xv.w - y3;
        acc = fmaf(d0, d0, acc);
        acc = fmaf(d1, d1, acc);
        acc = fmaf(d2, d2, acc);
        acc = fmaf(d3, d3, acc);
    }

    float v = sqrtf(acc);
    if (n == 1 || n == 2) v *= 1.5f;

    // ---- deterministic block reduction ----
#pragma unroll
    for (int off = 16; off > 0; off >>= 1)
        v += __shfl_down_sync(0xffffffffu, v, off);

    __shared__ float s_warp[THREADS / 32];
    if ((threadIdx.x & 31) == 0) s_warp[threadIdx.x >> 5] = v;
    __syncthreads();

    __shared__ bool s_is_last;
    if (threadIdx.x < THREADS / 32) {   // first 8 lanes
        v = s_warp[threadIdx.x];
#pragma unroll
        for (int off = (THREADS / 64); off > 0; off >>= 1)
            v += __shfl_down_sync(0x000000ffu, v, off);
        if (threadIdx.x == 0) {
            g_partials[blockIdx.x] = v;
            __threadfence();                       // make partial visible
            unsigned int prev = atomicAdd(&g_count, 1u);
            s_is_last = (prev == NBLK - 1);
        }
    }
    __syncthreads();

    if (!s_is_last) return;

    // ---- last block: reduce the 1024 partials in FIXED order ----
    // 256 threads, each sums 4 partials at fixed indices -> deterministic.
    __threadfence();  // order: counter observation before partial reads
    float s = g_partials[threadIdx.x]
            + g_partials[threadIdx.x + 256]
            + g_partials[threadIdx.x + 512]
            + g_partials[threadIdx.x + 768];

#pragma unroll
    for (int off = 16; off > 0; off >>= 1)
        s += __shfl_down_sync(0xffffffffu, s, off);

    if ((threadIdx.x & 31) == 0) s_warp[threadIdx.x >> 5] = s;
    __syncthreads();

    if (threadIdx.x < THREADS / 32) {
        s = s_warp[threadIdx.x];
#pragma unroll
        for (int off = (THREADS / 64); off > 0; off >>= 1)
            s += __shfl_down_sync(0x000000ffu, s, off);
        if (threadIdx.x == 0) {
            out[0] = s * (1.0f / ((float)B_DIM * (float)N_DIM));
            g_count = 0;   // re-arm for the next graph replay
        }
    }
}

extern "C" void kernel_launch(void* const* d_in, const int* in_sizes, int n_in,
                              void* d_out, int out_size) {
    const float* x = (const float*)d_in[0];
    const float* y = (const float*)d_in[1];
    float* out = (float*)d_out;

    euclid_fused_kernel<<<NBLK, THREADS>>>(x, y, out);
}